// round 2
// baseline (speedup 1.0000x reference)
#include <cuda_runtime.h>

#define NATOMS 768
#define H 100
#define IN_NODE 32
#define IN_EDGE 16
#define ITERS 3
#define NE (NATOMS * NATOMS)      // 589824

#define BM 128                     // rows of e per block in fused kernel
#define TM 8
#define TN 7
#define WPAD 112                   // padded col count for W tiles (16*TN)

// ---- scratch (device globals; no allocation allowed) ----
__device__ float g_dots[NE];                 // (768,768)
__device__ float g_fi[NATOMS * H];
__device__ float g_fj[NATOMS * H];
__device__ float g_PS[6 * NATOMS * H];       // per-segment partial row sums of e
__device__ float g_S[NATOMS * H];            // S[i] = sum_j e[i*N+j]
__device__ float g_dV[NATOMS * H];

// ---------------------------------------------------------------------------
// h = node_feats @ W_node + b_node     (768 x 32) @ (32 x 100)
__global__ void k_init_h(const float* __restrict__ nf, const float* __restrict__ W,
                         const float* __restrict__ b, float* __restrict__ h) {
    int idx = blockIdx.x * blockDim.x + threadIdx.x;
    if (idx >= NATOMS * H) return;
    int n = idx / H, c = idx % H;
    float acc = b[c];
#pragma unroll
    for (int k = 0; k < IN_NODE; k++) acc += nf[n * IN_NODE + k] * W[k * H + c];
    h[idx] = acc;
}

// e = edge_attr @ W_edge + b_edge      (589824 x 16) @ (16 x 100)
__global__ void k_init_e(const float* __restrict__ ea, const float* __restrict__ W,
                         const float* __restrict__ b, float* __restrict__ e) {
    __shared__ float sW[IN_EDGE * H];
    __shared__ float sb[H];
    for (int i = threadIdx.x; i < IN_EDGE * H; i += blockDim.x) sW[i] = W[i];
    for (int i = threadIdx.x; i < H; i += blockDim.x) sb[i] = b[i];
    __syncthreads();
    const int total = NE * H;  // 58,982,400 < 2^31
    for (int idx = blockIdx.x * blockDim.x + threadIdx.x; idx < total;
         idx += gridDim.x * blockDim.x) {
        int r = idx / H, c = idx % H;
        float acc = sb[c];
        const float* row = ea + r * IN_EDGE;
#pragma unroll
        for (int k = 0; k < IN_EDGE; k++) acc += __ldg(row + k) * sW[k * H + c];
        e[idx] = acc;
    }
}

// f_i = h @ W_i ; f_j = h @ W_j        (768 x 100) @ (100 x 100), no bias
__global__ void k_fij(const float* __restrict__ h, const float* __restrict__ Wi,
                      const float* __restrict__ Wj) {
    int idx = blockIdx.x * blockDim.x + threadIdx.x;
    if (idx >= 2 * NATOMS * H) return;
    int which = (idx < NATOMS * H) ? 0 : 1;
    int t = which ? (idx - NATOMS * H) : idx;
    const float* W = which ? Wj : Wi;
    float* out = which ? g_fj : g_fi;
    int n = t / H, c = t % H;
    float acc = 0.f;
#pragma unroll 4
    for (int k = 0; k < H; k++) acc += __ldg(h + n * H + k) * __ldg(W + k * H + c);
    out[t] = acc;
}

// dots[i][j] = dot(f_i[i], f_j[j])     (768 x 768), K = 100
__global__ void k_dots() {
    __shared__ float sA[16][17];
    __shared__ float sB[16][17];
    int tx = threadIdx.x, ty = threadIdx.y;
    int i = blockIdx.y * 16 + ty;
    int j = blockIdx.x * 16 + tx;
    float acc = 0.f;
    for (int k0 = 0; k0 < H; k0 += 16) {
        int ka = k0 + tx;
        sA[ty][tx] = (ka < H) ? g_fi[i * H + ka] : 0.f;
        int kb = k0 + ty;
        sB[ty][tx] = (kb < H) ? g_fj[j * H + kb] : 0.f;
        __syncthreads();
#pragma unroll
        for (int kk = 0; kk < 16; kk++) acc += sA[ty][kk] * sB[kk][tx];
        __syncthreads();
    }
    g_dots[i * NATOMS + j] = acc;
}

// ---------------------------------------------------------------------------
// Fused edge update for one 128-row tile of e (all rows share the same i):
//   f   = relu(e @ W_eij + b_eij + dots[i][j])
//   e  += f @ W_de + b_de
//   PS[seg][i][:] = sum over the tile's 128 rows of updated e
// smem layout: sE[BM*H] | sF[BM*H] | sW[H*WPAD] | sRed[16*WPAD]
extern __shared__ float smem[];

__global__ __launch_bounds__(256) void k_edge_fused(
    float* __restrict__ e,
    const float* __restrict__ W_eij, const float* __restrict__ b_eij,
    const float* __restrict__ W_de,  const float* __restrict__ b_de) {
    float* sE   = smem;
    float* sF   = sE + BM * H;
    float* sW   = sF + BM * H;
    float* sRed = sW + H * WPAD;

    const int tx = threadIdx.x, ty = threadIdx.y;
    const int tid = ty * 16 + tx;
    const int r0 = blockIdx.x * BM;              // first global edge row of tile
    const int i  = r0 / NATOMS;                  // 768 % 128 == 0 -> whole tile same i
    const int s  = (r0 % NATOMS) / BM;           // segment 0..5 within i

    // load e tile (contiguous 12800-float chunk)
    const int base = r0 * H;
    for (int idx = tid; idx < BM * H; idx += 256) sE[idx] = e[base + idx];
    // load W_eij, zero-padded to WPAD cols
    for (int idx = tid; idx < H * WPAD; idx += 256) {
        int k = idx / WPAD, c = idx % WPAD;
        sW[idx] = (c < H) ? W_eij[k * H + c] : 0.f;
    }
    __syncthreads();

    float acc[TM][TN];
#pragma unroll
    for (int m = 0; m < TM; m++)
#pragma unroll
        for (int n = 0; n < TN; n++) acc[m][n] = 0.f;

    // phase 1: f_ij = e @ W_eij
#pragma unroll 4
    for (int k = 0; k < H; k++) {
        float a[TM], bw[TN];
#pragma unroll
        for (int m = 0; m < TM; m++) a[m] = sE[(ty * TM + m) * H + k];
#pragma unroll
        for (int n = 0; n < TN; n++) bw[n] = sW[k * WPAD + tx * TN + n];
#pragma unroll
        for (int m = 0; m < TM; m++)
#pragma unroll
            for (int n = 0; n < TN; n++) acc[m][n] += a[m] * bw[n];
    }

    // + bias + dots broadcast, relu, stash into sF
    float d[TM];
#pragma unroll
    for (int m = 0; m < TM; m++)
        d[m] = g_dots[i * NATOMS + s * BM + ty * TM + m];
#pragma unroll
    for (int n = 0; n < TN; n++) {
        int c = tx * TN + n;
        if (c < H) {
            float bc = __ldg(b_eij + c);
#pragma unroll
            for (int m = 0; m < TM; m++) {
                float v = acc[m][n] + bc + d[m];
                sF[(ty * TM + m) * H + c] = fmaxf(v, 0.f);
            }
        }
    }
    __syncthreads();

    // swap in W_de
    for (int idx = tid; idx < H * WPAD; idx += 256) {
        int k = idx / WPAD, c = idx % WPAD;
        sW[idx] = (c < H) ? W_de[k * H + c] : 0.f;
    }
    __syncthreads();

#pragma unroll
    for (int m = 0; m < TM; m++)
#pragma unroll
        for (int n = 0; n < TN; n++) acc[m][n] = 0.f;

    // phase 2: delta = f @ W_de
#pragma unroll 4
    for (int k = 0; k < H; k++) {
        float a[TM], bw[TN];
#pragma unroll
        for (int m = 0; m < TM; m++) a[m] = sF[(ty * TM + m) * H + k];
#pragma unroll
        for (int n = 0; n < TN; n++) bw[n] = sW[k * WPAD + tx * TN + n];
#pragma unroll
        for (int m = 0; m < TM; m++)
#pragma unroll
            for (int n = 0; n < TN; n++) acc[m][n] += a[m] * bw[n];
    }

    // residual write-back + per-column partial sums for this tile
    float p[TN];
#pragma unroll
    for (int n = 0; n < TN; n++) p[n] = 0.f;
#pragma unroll
    for (int n = 0; n < TN; n++) {
        int c = tx * TN + n;
        if (c < H) {
            float bc = __ldg(b_de + c);
#pragma unroll
            for (int m = 0; m < TM; m++) {
                int row = ty * TM + m;
                float v = sE[row * H + c] + acc[m][n] + bc;
                e[base + row * H + c] = v;
                p[n] += v;
            }
        }
    }
    // deterministic tree reduce across ty
#pragma unroll
    for (int n = 0; n < TN; n++) sRed[ty * WPAD + tx * TN + n] = p[n];
    __syncthreads();
    if (tid < H) {
        float sum = 0.f;
#pragma unroll
        for (int t = 0; t < 16; t++) sum += sRed[t * WPAD + tid];
        g_PS[(s * NATOMS + i) * H + tid] = sum;
    }
}

// S[i][c] = sum over 6 segments
__global__ void k_reduce_S() {
    int idx = blockIdx.x * blockDim.x + threadIdx.x;
    if (idx >= NATOMS * H) return;
    float acc = 0.f;
#pragma unroll
    for (int seg = 0; seg < 6; seg++) acc += g_PS[seg * NATOMS * H + idx];
    g_S[idx] = acc;
}

// dV = S @ W_dv1 + N * b_dv1
__global__ void k_node1(const float* __restrict__ W, const float* __restrict__ b) {
    int idx = blockIdx.x * blockDim.x + threadIdx.x;
    if (idx >= NATOMS * H) return;
    int n = idx / H, c = idx % H;
    float acc = (float)NATOMS * __ldg(b + c);
#pragma unroll 4
    for (int k = 0; k < H; k++) acc += g_S[n * H + k] * __ldg(W + k * H + c);
    g_dV[idx] = acc;
}

// h += dV @ W_dv2 + b_dv2
__global__ void k_node2(float* __restrict__ h, const float* __restrict__ W,
                        const float* __restrict__ b) {
    int idx = blockIdx.x * blockDim.x + threadIdx.x;
    if (idx >= NATOMS * H) return;
    int n = idx / H, c = idx % H;
    float acc = __ldg(b + c);
#pragma unroll 4
    for (int k = 0; k < H; k++) acc += g_dV[n * H + k] * __ldg(W + k * H + c);
    h[idx] += acc;
}

// ---------------------------------------------------------------------------
extern "C" void kernel_launch(void* const* d_in, const int* in_sizes, int n_in,
                              void* d_out, int out_size) {
    const float* node_feats = (const float*)d_in[0];
    const float* edge_attr  = (const float*)d_in[1];
    const float* W_node = (const float*)d_in[2];
    const float* b_node = (const float*)d_in[3];
    const float* W_edge = (const float*)d_in[4];
    const float* b_edge = (const float*)d_in[5];
    const float* W_eij  = (const float*)d_in[6];
    const float* b_eij  = (const float*)d_in[7];
    const float* W_i    = (const float*)d_in[8];
    const float* W_j    = (const float*)d_in[9];
    const float* W_de   = (const float*)d_in[10];
    const float* b_de   = (const float*)d_in[11];
    const float* W_dv1  = (const float*)d_in[12];
    const float* b_dv1  = (const float*)d_in[13];
    const float* W_dv2  = (const float*)d_in[14];
    const float* b_dv2  = (const float*)d_in[15];

    float* h = (float*)d_out;            // (768, 100)
    float* e = h + NATOMS * H;           // (589824, 100), used in-place all iterations

    const int smem_bytes = (BM * H + BM * H + H * WPAD + 16 * WPAD) * (int)sizeof(float);
    cudaFuncSetAttribute(k_edge_fused, cudaFuncAttributeMaxDynamicSharedMemorySize,
                         smem_bytes);

    const int NH = NATOMS * H;
    k_init_h<<<(NH + 255) / 256, 256>>>(node_feats, W_node, b_node, h);
    k_init_e<<<4608, 256>>>(edge_attr, W_edge, b_edge, e);

    for (int it = 0; it < ITERS; it++) {
        k_fij<<<(2 * NH + 255) / 256, 256>>>(h, W_i, W_j);
        k_dots<<<dim3(48, 48), dim3(16, 16)>>>();
        k_edge_fused<<<NE / BM, dim3(16, 16), smem_bytes>>>(e, W_eij, b_eij, W_de, b_de);
        k_reduce_S<<<(NH + 255) / 256, 256>>>();
        k_node1<<<(NH + 255) / 256, 256>>>(W_dv1, b_dv1);
        k_node2<<<(NH + 255) / 256, 256>>>(h, W_dv2, b_dv2);
    }
}

// round 5
// speedup vs baseline: 1.1515x; 1.1515x over previous
#include <cuda_runtime.h>

#define NATOMS 768
#define H 100
#define IN_NODE 32
#define IN_EDGE 16
#define ITERS 3
#define NE (NATOMS * NATOMS)      // 589824

#define EPAD 104                   // padded H (13 * 8)
#define BM 128                     // e-rows per block in fused mma kernel
#define NT 13                      // n-tiles of 8
#define KC 13                      // k-chunks of 8

// ---- scratch (device globals; no allocation allowed) ----
__device__ float g_dots[NE];
__device__ float g_fi[NATOMS * H];
__device__ float g_fj[NATOMS * H];
__device__ float g_PS[6 * NATOMS * H];
__device__ float g_S[NATOMS * H];
__device__ float g_dV[NATOMS * H];
// tf32-split weights, padded to 104x104, zero-filled pads
__device__ float g_Weij_hi[EPAD * EPAD];
__device__ float g_Weij_lo[EPAD * EPAD];
__device__ float g_Wde_hi[EPAD * EPAD];
__device__ float g_Wde_lo[EPAD * EPAD];

// ---------------------------------------------------------------------------
__device__ __forceinline__ void split_tf32(float v, unsigned& hi, unsigned& lo) {
    asm("cvt.rna.tf32.f32 %0, %1;" : "=r"(hi) : "f"(v));
    float l = v - __uint_as_float(hi);
    asm("cvt.rna.tf32.f32 %0, %1;" : "=r"(lo) : "f"(l));
}

__device__ __forceinline__ void mma_tf32(float* d, const unsigned* a,
                                         unsigned b0, unsigned b1) {
    asm volatile(
        "mma.sync.aligned.m16n8k8.row.col.f32.tf32.tf32.f32 "
        "{%0,%1,%2,%3},{%4,%5,%6,%7},{%8,%9},{%0,%1,%2,%3};"
        : "+f"(d[0]), "+f"(d[1]), "+f"(d[2]), "+f"(d[3])
        : "r"(a[0]), "r"(a[1]), "r"(a[2]), "r"(a[3]), "r"(b0), "r"(b1));
}

// ---------------------------------------------------------------------------
// Precompute tf32 hi/lo splits of W_eij / W_de into padded 104x104 globals.
// which==0 -> W_eij, which==1 -> W_de.
__global__ void k_split_w(const float* __restrict__ W, int which) {
    int idx = blockIdx.x * blockDim.x + threadIdx.x;
    if (idx >= EPAD * EPAD) return;
    int k = idx / EPAD, n = idx % EPAD;
    float v = (k < H && n < H) ? W[k * H + n] : 0.f;
    unsigned h, l;
    split_tf32(v, h, l);
    if (which == 0) {
        g_Weij_hi[idx] = __uint_as_float(h);
        g_Weij_lo[idx] = __uint_as_float(l);
    } else {
        g_Wde_hi[idx] = __uint_as_float(h);
        g_Wde_lo[idx] = __uint_as_float(l);
    }
}

// h = node_feats @ W_node + b_node
__global__ void k_init_h(const float* __restrict__ nf, const float* __restrict__ W,
                         const float* __restrict__ b, float* __restrict__ h) {
    int idx = blockIdx.x * blockDim.x + threadIdx.x;
    if (idx >= NATOMS * H) return;
    int n = idx / H, c = idx % H;
    float acc = b[c];
#pragma unroll
    for (int k = 0; k < IN_NODE; k++) acc += nf[n * IN_NODE + k] * W[k * H + c];
    h[idx] = acc;
}

// e = edge_attr @ W_edge + b_edge
__global__ void k_init_e(const float* __restrict__ ea, const float* __restrict__ W,
                         const float* __restrict__ b, float* __restrict__ e) {
    __shared__ float sW[IN_EDGE * H];
    __shared__ float sb[H];
    for (int i = threadIdx.x; i < IN_EDGE * H; i += blockDim.x) sW[i] = W[i];
    for (int i = threadIdx.x; i < H; i += blockDim.x) sb[i] = b[i];
    __syncthreads();
    const int total = NE * H;
    for (int idx = blockIdx.x * blockDim.x + threadIdx.x; idx < total;
         idx += gridDim.x * blockDim.x) {
        int r = idx / H, c = idx % H;
        float acc = sb[c];
        const float* row = ea + r * IN_EDGE;
#pragma unroll
        for (int k = 0; k < IN_EDGE; k++) acc += __ldg(row + k) * sW[k * H + c];
        e[idx] = acc;
    }
}

// f_i = h @ W_i ; f_j = h @ W_j
__global__ void k_fij(const float* __restrict__ h, const float* __restrict__ Wi,
                      const float* __restrict__ Wj) {
    int idx = blockIdx.x * blockDim.x + threadIdx.x;
    if (idx >= 2 * NATOMS * H) return;
    int which = (idx < NATOMS * H) ? 0 : 1;
    int t = which ? (idx - NATOMS * H) : idx;
    const float* W = which ? Wj : Wi;
    float* out = which ? g_fj : g_fi;
    int n = t / H, c = t % H;
    float acc = 0.f;
#pragma unroll 4
    for (int k = 0; k < H; k++) acc += __ldg(h + n * H + k) * __ldg(W + k * H + c);
    out[t] = acc;
}

// dots[i][j] = dot(f_i[i], f_j[j])
__global__ void k_dots() {
    __shared__ float sA[16][17];
    __shared__ float sB[16][17];
    int tx = threadIdx.x, ty = threadIdx.y;
    int i = blockIdx.y * 16 + ty;
    int j = blockIdx.x * 16 + tx;
    float acc = 0.f;
    for (int k0 = 0; k0 < H; k0 += 16) {
        int ka = k0 + tx;
        sA[ty][tx] = (ka < H) ? g_fi[i * H + ka] : 0.f;
        int kb = k0 + ty;
        sB[ty][tx] = (kb < H) ? g_fj[j * H + kb] : 0.f;
        __syncthreads();
#pragma unroll
        for (int kk = 0; kk < 16; kk++) acc += sA[ty][kk] * sB[kk][tx];
        __syncthreads();
    }
    g_dots[i * NATOMS + j] = acc;
}

// ---------------------------------------------------------------------------
// Fused edge update, 3xTF32 tensor-core version.
//   f   = relu(e @ W_eij + b_eij + dots)
//   e  += f @ W_de + b_de
//   PS[seg][i][:] = column sums of the updated 128-row tile
//
// Block: 256 threads = 8 warps, each warp owns 16 rows (one m16 tile).
// smem: sE[128*104] | sF[128*104] | sWh[104*104] | sWl[104*104]
extern __shared__ float smem[];

__global__ __launch_bounds__(256) void k_edge_mma(
    float* __restrict__ e,
    const float* __restrict__ b_eij, const float* __restrict__ b_de) {
    float* sE = smem;
    float* sF = sE + BM * EPAD;
    float* sWh = sF + BM * EPAD;
    float* sWl = sWh + EPAD * EPAD;

    const int tid = threadIdx.x;
    const int w = tid >> 5;
    const int lane = tid & 31;
    const int g = lane >> 2;
    const int tig = lane & 3;

    const int r0 = blockIdx.x * BM;
    const int i = r0 / NATOMS;
    const int s = (r0 % NATOMS) / BM;
    const size_t base = (size_t)r0 * H;

    // stage E tile (zero-padded cols) and W_eij split
    for (int idx = tid; idx < BM * EPAD; idx += 256) {
        int r = idx / EPAD, c = idx - r * EPAD;
        sE[idx] = (c < H) ? e[base + r * H + c] : 0.f;
    }
    for (int idx = tid; idx < EPAD * EPAD; idx += 256) {
        sWh[idx] = g_Weij_hi[idx];
        sWl[idx] = g_Weij_lo[idx];
    }
    __syncthreads();

    const int row0 = w * 16 + g;     // this thread's upper row within tile
    float acc[NT][4];
#pragma unroll
    for (int n = 0; n < NT; n++)
#pragma unroll
        for (int q = 0; q < 4; q++) acc[n][q] = 0.f;

    // ---- phase 1: acc = E @ W_eij ----
#pragma unroll
    for (int kc = 0; kc < KC; kc++) {
        unsigned ahi[4], alo[4];
        int c0 = kc * 8 + tig;
        split_tf32(sE[row0 * EPAD + c0], ahi[0], alo[0]);
        split_tf32(sE[(row0 + 8) * EPAD + c0], ahi[1], alo[1]);
        split_tf32(sE[row0 * EPAD + c0 + 4], ahi[2], alo[2]);
        split_tf32(sE[(row0 + 8) * EPAD + c0 + 4], ahi[3], alo[3]);
#pragma unroll
        for (int n = 0; n < NT; n++) {
            int bi = (kc * 8 + tig) * EPAD + n * 8 + g;
            unsigned b0h = __float_as_uint(sWh[bi]);
            unsigned b1h = __float_as_uint(sWh[bi + 4 * EPAD]);
            unsigned b0l = __float_as_uint(sWl[bi]);
            unsigned b1l = __float_as_uint(sWl[bi + 4 * EPAD]);
            mma_tf32(acc[n], ahi, b0h, b1h);
            mma_tf32(acc[n], ahi, b0l, b1l);
            mma_tf32(acc[n], alo, b0h, b1h);
        }
    }

    // bias + dots + relu -> sF (explicit zeros in pad cols)
    {
        float d0 = g_dots[i * NATOMS + s * BM + row0];
        float d1 = g_dots[i * NATOMS + s * BM + row0 + 8];
#pragma unroll
        for (int n = 0; n < NT; n++) {
            int c0 = n * 8 + 2 * tig, c1 = c0 + 1;
            float be0 = (c0 < H) ? __ldg(b_eij + c0) : 0.f;
            float be1 = (c1 < H) ? __ldg(b_eij + c1) : 0.f;
            float f00 = (c0 < H) ? fmaxf(acc[n][0] + be0 + d0, 0.f) : 0.f;
            float f01 = (c1 < H) ? fmaxf(acc[n][1] + be1 + d0, 0.f) : 0.f;
            float f10 = (c0 < H) ? fmaxf(acc[n][2] + be0 + d1, 0.f) : 0.f;
            float f11 = (c1 < H) ? fmaxf(acc[n][3] + be1 + d1, 0.f) : 0.f;
            sF[row0 * EPAD + c0] = f00;
            sF[row0 * EPAD + c1] = f01;
            sF[(row0 + 8) * EPAD + c0] = f10;
            sF[(row0 + 8) * EPAD + c1] = f11;
        }
    }
    __syncthreads();

    // swap weights to W_de split
    for (int idx = tid; idx < EPAD * EPAD; idx += 256) {
        sWh[idx] = g_Wde_hi[idx];
        sWl[idx] = g_Wde_lo[idx];
    }
    __syncthreads();

#pragma unroll
    for (int n = 0; n < NT; n++)
#pragma unroll
        for (int q = 0; q < 4; q++) acc[n][q] = 0.f;

    // ---- phase 2: acc = F @ W_de ----
#pragma unroll
    for (int kc = 0; kc < KC; kc++) {
        unsigned ahi[4], alo[4];
        int c0 = kc * 8 + tig;
        split_tf32(sF[row0 * EPAD + c0], ahi[0], alo[0]);
        split_tf32(sF[(row0 + 8) * EPAD + c0], ahi[1], alo[1]);
        split_tf32(sF[row0 * EPAD + c0 + 4], ahi[2], alo[2]);
        split_tf32(sF[(row0 + 8) * EPAD + c0 + 4], ahi[3], alo[3]);
#pragma unroll
        for (int n = 0; n < NT; n++) {
            int bi = (kc * 8 + tig) * EPAD + n * 8 + g;
            unsigned b0h = __float_as_uint(sWh[bi]);
            unsigned b1h = __float_as_uint(sWh[bi + 4 * EPAD]);
            unsigned b0l = __float_as_uint(sWl[bi]);
            unsigned b1l = __float_as_uint(sWl[bi + 4 * EPAD]);
            mma_tf32(acc[n], ahi, b0h, b1h);
            mma_tf32(acc[n], ahi, b0l, b1l);
            mma_tf32(acc[n], alo, b0h, b1h);
        }
    }

    __syncthreads();  // everyone done reading sW (about to reuse as reduce scratch)

    // ---- residual writeback + deterministic column sums ----
    // sWh reused as sRed[8 warps][EPAD]
#pragma unroll
    for (int n = 0; n < NT; n++) {
        int c0 = n * 8 + 2 * tig, c1 = c0 + 1;
        float p0 = 0.f, p1 = 0.f;
        if (c0 < H) {
            float bd = __ldg(b_de + c0);
            float v0 = sE[row0 * EPAD + c0] + acc[n][0] + bd;
            float v1 = sE[(row0 + 8) * EPAD + c0] + acc[n][2] + bd;
            e[base + row0 * H + c0] = v0;
            e[base + (row0 + 8) * H + c0] = v1;
            p0 = v0 + v1;
        }
        if (c1 < H) {
            float bd = __ldg(b_de + c1);
            float v0 = sE[row0 * EPAD + c1] + acc[n][1] + bd;
            float v1 = sE[(row0 + 8) * EPAD + c1] + acc[n][3] + bd;
            e[base + row0 * H + c1] = v0;
            e[base + (row0 + 8) * H + c1] = v1;
            p1 = v0 + v1;
        }
        // reduce over the 8 groups (lanes with equal tig)
        p0 += __shfl_down_sync(0xffffffff, p0, 16);
        p0 += __shfl_down_sync(0xffffffff, p0, 8);
        p0 += __shfl_down_sync(0xffffffff, p0, 4);
        p1 += __shfl_down_sync(0xffffffff, p1, 16);
        p1 += __shfl_down_sync(0xffffffff, p1, 8);
        p1 += __shfl_down_sync(0xffffffff, p1, 4);
        if (lane < 4) {
            sWh[w * EPAD + c0] = p0;
            sWh[w * EPAD + c1] = p1;
        }
    }
    __syncthreads();

    if (tid < H) {
        float sum = 0.f;
#pragma unroll
        for (int t = 0; t < 8; t++) sum += sWh[t * EPAD + tid];
        g_PS[(s * NATOMS + i) * H + tid] = sum;
    }
}

// ---------------------------------------------------------------------------
__global__ void k_reduce_S() {
    int idx = blockIdx.x * blockDim.x + threadIdx.x;
    if (idx >= NATOMS * H) return;
    float acc = 0.f;
#pragma unroll
    for (int seg = 0; seg < 6; seg++) acc += g_PS[seg * NATOMS * H + idx];
    g_S[idx] = acc;
}

__global__ void k_node1(const float* __restrict__ W, const float* __restrict__ b) {
    int idx = blockIdx.x * blockDim.x + threadIdx.x;
    if (idx >= NATOMS * H) return;
    int n = idx / H, c = idx % H;
    float acc = (float)NATOMS * __ldg(b + c);
#pragma unroll 4
    for (int k = 0; k < H; k++) acc += g_S[n * H + k] * __ldg(W + k * H + c);
    g_dV[idx] = acc;
}

__global__ void k_node2(float* __restrict__ h, const float* __restrict__ W,
                        const float* __restrict__ b) {
    int idx = blockIdx.x * blockDim.x + threadIdx.x;
    if (idx >= NATOMS * H) return;
    int n = idx / H, c = idx % H;
    float acc = __ldg(b + c);
#pragma unroll 4
    for (int k = 0; k < H; k++) acc += g_dV[n * H + k] * __ldg(W + k * H + c);
    h[idx] += acc;
}

// ---------------------------------------------------------------------------
extern "C" void kernel_launch(void* const* d_in, const int* in_sizes, int n_in,
                              void* d_out, int out_size) {
    const float* node_feats = (const float*)d_in[0];
    const float* edge_attr  = (const float*)d_in[1];
    const float* W_node = (const float*)d_in[2];
    const float* b_node = (const float*)d_in[3];
    const float* W_edge = (const float*)d_in[4];
    const float* b_edge = (const float*)d_in[5];
    const float* W_eij  = (const float*)d_in[6];
    const float* b_eij  = (const float*)d_in[7];
    const float* W_i    = (const float*)d_in[8];
    const float* W_j    = (const float*)d_in[9];
    const float* W_de   = (const float*)d_in[10];
    const float* b_de   = (const float*)d_in[11];
    const float* W_dv1  = (const float*)d_in[12];
    const float* b_dv1  = (const float*)d_in[13];
    const float* W_dv2  = (const float*)d_in[14];
    const float* b_dv2  = (const float*)d_in[15];

    float* h = (float*)d_out;            // (768, 100)
    float* e = h + NATOMS * H;           // (589824, 100)

    const int smem_bytes = (2 * BM * EPAD + 2 * EPAD * EPAD) * (int)sizeof(float);
    cudaFuncSetAttribute(k_edge_mma, cudaFuncAttributeMaxDynamicSharedMemorySize,
                         smem_bytes);

    const int NH = NATOMS * H;
    const int WP = (EPAD * EPAD + 255) / 256;

    // weight splits (constant across iterations; recomputed every call for
    // determinism under graph replay)
    k_split_w<<<WP, 256>>>(W_eij, 0);
    k_split_w<<<WP, 256>>>(W_de, 1);

    k_init_h<<<(NH + 255) / 256, 256>>>(node_feats, W_node, b_node, h);
    k_init_e<<<4608, 256>>>(edge_attr, W_edge, b_edge, e);

    for (int it = 0; it < ITERS; it++) {
        k_fij<<<(2 * NH + 255) / 256, 256>>>(h, W_i, W_j);
        k_dots<<<dim3(48, 48), dim3(16, 16)>>>();
        k_edge_mma<<<NE / BM, 256, smem_bytes>>>(e, b_eij, b_de);
        k_reduce_S<<<(NH + 255) / 256, 256>>>();
        k_node1<<<(NH + 255) / 256, 256>>>(W_dv1, b_dv1);
        k_node2<<<(NH + 255) / 256, 256>>>(h, W_dv2, b_dv2);
    }
}

// round 8
// speedup vs baseline: 2.0474x; 1.7780x over previous
#include <cuda_runtime.h>
#include <cuda_bf16.h>

#define NATOMS 768
#define H 100
#define IN_NODE 32
#define IN_EDGE 16
#define ITERS 3
#define NE (NATOMS * NATOMS)       // 589824

#define BM 128                      // e-rows per tile
#define NTILES (NE / BM)            // 4608
#define SEGS 6                      // 768 / 128
#define NT 13                       // n-tiles of 8 (cols 0..103)
#define KC 7                        // k-chunks of 16 (cols 0..111)
#define RS 58                       // row stride in u32 words (116 bf16) for E/F/W

// ---- scratch (device globals; no allocation allowed) ----
__device__ float g_dots[NE];
__device__ float g_fi[NATOMS * H];
__device__ float g_fj[NATOMS * H];
__device__ float g_PS[SEGS * NATOMS * H];
__device__ float g_S[NATOMS * H];
__device__ float g_dV[NATOMS * H];
// bf16 hi/lo split weights, n-major, padded to 104(n) x 116(k)
__device__ __nv_bfloat16 g_Weij_h[104 * 116];
__device__ __nv_bfloat16 g_Weij_l[104 * 116];
__device__ __nv_bfloat16 g_Wde_h[104 * 116];
__device__ __nv_bfloat16 g_Wde_l[104 * 116];

// ---------------------------------------------------------------------------
__device__ __forceinline__ void mma_bf16(float* d, unsigned a0, unsigned a1,
                                         unsigned a2, unsigned a3,
                                         unsigned b0, unsigned b1) {
    asm volatile(
        "mma.sync.aligned.m16n8k16.row.col.f32.bf16.bf16.f32 "
        "{%0,%1,%2,%3},{%4,%5,%6,%7},{%8,%9},{%0,%1,%2,%3};"
        : "+f"(d[0]), "+f"(d[1]), "+f"(d[2]), "+f"(d[3])
        : "r"(a0), "r"(a1), "r"(a2), "r"(a3), "r"(b0), "r"(b1));
}

// split x,y into bf16 hi/lo pairs packed as u32 (lo = bf16(v - hi))
__device__ __forceinline__ void split_pack(float x, float y, unsigned& hi,
                                           unsigned& lo) {
    __nv_bfloat16 hx = __float2bfloat16(x), hy = __float2bfloat16(y);
    float lx = x - __bfloat162float(hx);
    float ly = y - __bfloat162float(hy);
    __nv_bfloat162 Hp = __halves2bfloat162(hx, hy);
    __nv_bfloat162 Lp = __halves2bfloat162(__float2bfloat16(lx),
                                           __float2bfloat16(ly));
    hi = *reinterpret_cast<unsigned*>(&Hp);
    lo = *reinterpret_cast<unsigned*>(&Lp);
}

// ---------------------------------------------------------------------------
// Split 100x100 fp32 weight into bf16 hi/lo, n-major, padded 104x116.
__global__ void k_split_w(const float* __restrict__ W, int which) {
    int idx = blockIdx.x * blockDim.x + threadIdx.x;
    if (idx >= 104 * 116) return;
    int n = idx / 116, k = idx % 116;
    float v = (k < H && n < H) ? W[k * H + n] : 0.f;
    __nv_bfloat16 h = __float2bfloat16(v);
    __nv_bfloat16 l = __float2bfloat16(v - __bfloat162float(h));
    if (which == 0) { g_Weij_h[idx] = h; g_Weij_l[idx] = l; }
    else           { g_Wde_h[idx]  = h; g_Wde_l[idx]  = l; }
}

// h = node_feats @ W_node + b_node
__global__ void k_init_h(const float* __restrict__ nf, const float* __restrict__ W,
                         const float* __restrict__ b, float* __restrict__ h) {
    int idx = blockIdx.x * blockDim.x + threadIdx.x;
    if (idx >= NATOMS * H) return;
    int n = idx / H, c = idx % H;
    float acc = b[c];
#pragma unroll
    for (int k = 0; k < IN_NODE; k++) acc += nf[n * IN_NODE + k] * W[k * H + c];
    h[idx] = acc;
}

// f_i = h @ W_i ; f_j = h @ W_j
__global__ void k_fij(const float* __restrict__ h, const float* __restrict__ Wi,
                      const float* __restrict__ Wj) {
    int idx = blockIdx.x * blockDim.x + threadIdx.x;
    if (idx >= 2 * NATOMS * H) return;
    int which = (idx < NATOMS * H) ? 0 : 1;
    int t = which ? (idx - NATOMS * H) : idx;
    const float* W = which ? Wj : Wi;
    float* out = which ? g_fj : g_fi;
    int n = t / H, c = t % H;
    float acc = 0.f;
#pragma unroll 4
    for (int k = 0; k < H; k++) acc += __ldg(h + n * H + k) * __ldg(W + k * H + c);
    out[t] = acc;
}

// dots[i][j] = dot(f_i[i], f_j[j])
__global__ void k_dots() {
    __shared__ float sA[16][17];
    __shared__ float sB[16][17];
    int tx = threadIdx.x, ty = threadIdx.y;
    int i = blockIdx.y * 16 + ty;
    int j = blockIdx.x * 16 + tx;
    float acc = 0.f;
    for (int k0 = 0; k0 < H; k0 += 16) {
        int ka = k0 + tx;
        sA[ty][tx] = (ka < H) ? g_fi[i * H + ka] : 0.f;
        int kb = k0 + ty;
        sB[ty][tx] = (kb < H) ? g_fj[j * H + kb] : 0.f;
        __syncthreads();
#pragma unroll
        for (int kk = 0; kk < 16; kk++) acc += sA[ty][kk] * sB[kk][tx];
        __syncthreads();
    }
    g_dots[i * NATOMS + j] = acc;
}

// ---------------------------------------------------------------------------
// Persistent fused edge kernel (bf16 3-term split, m16n8k16 tensor cores).
// For each 128-row tile of e:
//   iter0: E = ea_tile @ W_edge + b_edge (computed in-kernel), else E = e tile
//   F  = relu(E @ W_eij + b_eij + dots)
//   e' = E + F @ W_de + b_de      (written back; column sums -> g_PS)
//
// smem (u32 words): sEh[7424] sEl[7424] sFh[7424] sFl[7424]
//                   sW[4*6032] (Weij_h, Weij_l, Wde_h, Wde_l; n-major)
//                   sRed[832 f32], sWe[1600 f32], sbe[100 f32]
extern __shared__ unsigned usmem[];

__global__ __launch_bounds__(256) void k_edge(
    float* __restrict__ e, const float* __restrict__ ea,
    const float* __restrict__ W_edge, const float* __restrict__ b_edge,
    const float* __restrict__ b_eij, const float* __restrict__ b_de, int first) {
    unsigned* sEh = usmem;
    unsigned* sEl = sEh + BM * RS;
    unsigned* sFh = sEl + BM * RS;
    unsigned* sFl = sFh + BM * RS;
    unsigned* sW  = sFl + BM * RS;                 // 4 * 6032
    float* sRed = (float*)(sW + 4 * 104 * RS);     // 8 * 104
    float* sWe  = sRed + 8 * 104;                  // 100 * 16 (c-major)
    float* sbe  = sWe + 1600;                      // 100

    const int tid = threadIdx.x;
    const int w = tid >> 5;
    const int lane = tid & 31;
    const int g = lane >> 2;
    const int tig = lane & 3;
    const int rA = w * 16 + g;                     // upper row of this thread

    // ---- stage all weights once ----
    for (int idx = tid; idx < 104 * RS; idx += 256) {
        sW[idx]              = ((const unsigned*)g_Weij_h)[idx];
        sW[104 * RS + idx]   = ((const unsigned*)g_Weij_l)[idx];
        sW[2 * 104 * RS + idx] = ((const unsigned*)g_Wde_h)[idx];
        sW[3 * 104 * RS + idx] = ((const unsigned*)g_Wde_l)[idx];
    }
    for (int idx = tid; idx < 1600; idx += 256) {
        int c = idx / 16, k = idx % 16;
        sWe[idx] = W_edge[k * H + c];
    }
    if (tid < H) sbe[tid] = b_edge[tid];
    __syncthreads();

    for (int t = blockIdx.x; t < NTILES; t += gridDim.x) {
        const int i = t / SEGS;
        const int s = t % SEGS;
        const size_t base = (size_t)t * BM * H;

        // ---- stage E tile (split bf16 hi/lo) ----
        if (first) {
            // E = ea_row @ W_edge + b_edge; 2 threads per row, 58 cols each
            int r = tid >> 1, half = tid & 1;
            float a[16];
            const float4* ear = (const float4*)(ea + ((size_t)t * BM + r) * IN_EDGE);
            float4 q0 = ear[0], q1 = ear[1], q2 = ear[2], q3 = ear[3];
            a[0]=q0.x;a[1]=q0.y;a[2]=q0.z;a[3]=q0.w; a[4]=q1.x;a[5]=q1.y;a[6]=q1.z;a[7]=q1.w;
            a[8]=q2.x;a[9]=q2.y;a[10]=q2.z;a[11]=q2.w; a[12]=q3.x;a[13]=q3.y;a[14]=q3.z;a[15]=q3.w;
            int cb = half * RS;   // 0 or 58 (even)
            for (int cc = 0; cc < RS; cc += 2) {
                int c0 = cb + cc;
                float v0 = 0.f, v1 = 0.f;
                if (c0 < H) {
                    v0 = sbe[c0]; v1 = sbe[c0 + 1];
#pragma unroll
                    for (int k = 0; k < 16; k++) {
                        v0 += a[k] * sWe[c0 * 16 + k];
                        v1 += a[k] * sWe[(c0 + 1) * 16 + k];
                    }
                }
                unsigned hi, lo;
                split_pack(v0, v1, hi, lo);
                sEh[r * RS + (c0 >> 1)] = hi;
                sEl[r * RS + (c0 >> 1)] = lo;
            }
        } else {
            for (int idx = tid; idx < BM * RS; idx += 256) {
                int r = idx / RS, wd = idx - r * RS;
                int c = wd * 2;
                float v0 = 0.f, v1 = 0.f;
                if (c < H) {
                    float2 p = *(const float2*)(e + base + r * H + c);
                    v0 = p.x; v1 = p.y;
                }
                unsigned hi, lo;
                split_pack(v0, v1, hi, lo);
                sEh[idx] = hi;
                sEl[idx] = lo;
            }
        }
        // zero F pad cols 104..111 (words 52..55)
        for (int idx = tid; idx < BM * 4; idx += 256) {
            int r = idx >> 2, wd = 52 + (idx & 3);
            sFh[r * RS + wd] = 0u;
            sFl[r * RS + wd] = 0u;
        }
        __syncthreads();

        // ---- phase 1: acc = E @ W_eij (3-term bf16) ----
        float acc[NT][4];
#pragma unroll
        for (int n = 0; n < NT; n++)
#pragma unroll
            for (int q = 0; q < 4; q++) acc[n][q] = 0.f;

#pragma unroll
        for (int kc = 0; kc < KC; kc++) {
            int ab = rA * RS + kc * 8 + tig;
            unsigned ah0 = sEh[ab],       ah1 = sEh[ab + 8 * RS];
            unsigned ah2 = sEh[ab + 4],   ah3 = sEh[ab + 8 * RS + 4];
            unsigned al0 = sEl[ab],       al1 = sEl[ab + 8 * RS];
            unsigned al2 = sEl[ab + 4],   al3 = sEl[ab + 8 * RS + 4];
#pragma unroll
            for (int n = 0; n < NT; n++) {
                int bb = (n * 8 + g) * RS + kc * 8 + tig;
                unsigned bh0 = sW[bb], bh1 = sW[bb + 4];
                unsigned bl0 = sW[104 * RS + bb], bl1 = sW[104 * RS + bb + 4];
                mma_bf16(acc[n], ah0, ah1, ah2, ah3, bh0, bh1);
                mma_bf16(acc[n], ah0, ah1, ah2, ah3, bl0, bl1);
                mma_bf16(acc[n], al0, al1, al2, al3, bh0, bh1);
            }
        }

        // ---- F = relu(acc + b_eij + dots), split -> sF ----
        {
            float d0 = g_dots[i * NATOMS + s * BM + rA];
            float d1 = g_dots[i * NATOMS + s * BM + rA + 8];
#pragma unroll
            for (int n = 0; n < NT; n++) {
                int c0 = n * 8 + tig * 2;
                float f00 = 0.f, f01 = 0.f, f10 = 0.f, f11 = 0.f;
                if (c0 < H) {
                    float be0 = __ldg(b_eij + c0), be1 = __ldg(b_eij + c0 + 1);
                    f00 = fmaxf(acc[n][0] + be0 + d0, 0.f);
                    f01 = fmaxf(acc[n][1] + be1 + d0, 0.f);
                    f10 = fmaxf(acc[n][2] + be0 + d1, 0.f);
                    f11 = fmaxf(acc[n][3] + be1 + d1, 0.f);
                }
                unsigned hi, lo;
                int wi = rA * RS + n * 4 + tig;
                split_pack(f00, f01, hi, lo);
                sFh[wi] = hi; sFl[wi] = lo;
                split_pack(f10, f11, hi, lo);
                sFh[wi + 8 * RS] = hi; sFl[wi + 8 * RS] = lo;
            }
        }
        __syncthreads();

        // ---- phase 2: acc = F @ W_de ----
#pragma unroll
        for (int n = 0; n < NT; n++)
#pragma unroll
            for (int q = 0; q < 4; q++) acc[n][q] = 0.f;

#pragma unroll
        for (int kc = 0; kc < KC; kc++) {
            int ab = rA * RS + kc * 8 + tig;
            unsigned ah0 = sFh[ab],       ah1 = sFh[ab + 8 * RS];
            unsigned ah2 = sFh[ab + 4],   ah3 = sFh[ab + 8 * RS + 4];
            unsigned al0 = sFl[ab],       al1 = sFl[ab + 8 * RS];
            unsigned al2 = sFl[ab + 4],   al3 = sFl[ab + 8 * RS + 4];
#pragma unroll
            for (int n = 0; n < NT; n++) {
                int bb = (n * 8 + g) * RS + kc * 8 + tig;
                unsigned bh0 = sW[2 * 104 * RS + bb], bh1 = sW[2 * 104 * RS + bb + 4];
                unsigned bl0 = sW[3 * 104 * RS + bb], bl1 = sW[3 * 104 * RS + bb + 4];
                mma_bf16(acc[n], ah0, ah1, ah2, ah3, bh0, bh1);
                mma_bf16(acc[n], ah0, ah1, ah2, ah3, bl0, bl1);
                mma_bf16(acc[n], al0, al1, al2, al3, bh0, bh1);
            }
        }

        // ---- residual writeback + column sums ----
#pragma unroll
        for (int n = 0; n < NT; n++) {
            int c0 = n * 8 + tig * 2;
            float p0 = 0.f, p1 = 0.f;
            if (c0 < H) {
                float bd0 = __ldg(b_de + c0), bd1 = __ldg(b_de + c0 + 1);
                int wi = rA * RS + n * 4 + tig;
                __nv_bfloat162 Eh0 = *reinterpret_cast<__nv_bfloat162*>(&sEh[wi]);
                __nv_bfloat162 El0 = *reinterpret_cast<__nv_bfloat162*>(&sEl[wi]);
                __nv_bfloat162 Eh1 = *reinterpret_cast<__nv_bfloat162*>(&sEh[wi + 8 * RS]);
                __nv_bfloat162 El1 = *reinterpret_cast<__nv_bfloat162*>(&sEl[wi + 8 * RS]);
                float e00 = __low2float(Eh0) + __low2float(El0);
                float e01 = __high2float(Eh0) + __high2float(El0);
                float e10 = __low2float(Eh1) + __low2float(El1);
                float e11 = __high2float(Eh1) + __high2float(El1);
                float v00 = e00 + acc[n][0] + bd0;
                float v01 = e01 + acc[n][1] + bd1;
                float v10 = e10 + acc[n][2] + bd0;
                float v11 = e11 + acc[n][3] + bd1;
                *(float2*)(e + base + rA * H + c0) = make_float2(v00, v01);
                *(float2*)(e + base + (rA + 8) * H + c0) = make_float2(v10, v11);
                p0 = v00 + v10;
                p1 = v01 + v11;
            }
            p0 += __shfl_down_sync(0xffffffffu, p0, 16);
            p0 += __shfl_down_sync(0xffffffffu, p0, 8);
            p0 += __shfl_down_sync(0xffffffffu, p0, 4);
            p1 += __shfl_down_sync(0xffffffffu, p1, 16);
            p1 += __shfl_down_sync(0xffffffffu, p1, 8);
            p1 += __shfl_down_sync(0xffffffffu, p1, 4);
            if (lane < 4 && c0 < H) {
                sRed[w * 104 + c0] = p0;
                sRed[w * 104 + c0 + 1] = p1;
            }
        }
        __syncthreads();

        if (tid < H) {
            float sum = 0.f;
#pragma unroll
            for (int q = 0; q < 8; q++) sum += sRed[q * 104 + tid];
            g_PS[(s * NATOMS + i) * H + tid] = sum;
        }
        __syncthreads();
    }
}

// ---------------------------------------------------------------------------
__global__ void k_reduce_S() {
    int idx = blockIdx.x * blockDim.x + threadIdx.x;
    if (idx >= NATOMS * H) return;
    float acc = 0.f;
#pragma unroll
    for (int seg = 0; seg < SEGS; seg++) acc += g_PS[seg * NATOMS * H + idx];
    g_S[idx] = acc;
}

__global__ void k_node1(const float* __restrict__ W, const float* __restrict__ b) {
    int idx = blockIdx.x * blockDim.x + threadIdx.x;
    if (idx >= NATOMS * H) return;
    int n = idx / H, c = idx % H;
    float acc = (float)NATOMS * __ldg(b + c);
#pragma unroll 4
    for (int k = 0; k < H; k++) acc += g_S[n * H + k] * __ldg(W + k * H + c);
    g_dV[idx] = acc;
}

__global__ void k_node2(float* __restrict__ h, const float* __restrict__ W,
                        const float* __restrict__ b) {
    int idx = blockIdx.x * blockDim.x + threadIdx.x;
    if (idx >= NATOMS * H) return;
    int n = idx / H, c = idx % H;
    float acc = __ldg(b + c);
#pragma unroll 4
    for (int k = 0; k < H; k++) acc += g_dV[n * H + k] * __ldg(W + k * H + c);
    h[idx] += acc;
}

// ---------------------------------------------------------------------------
extern "C" void kernel_launch(void* const* d_in, const int* in_sizes, int n_in,
                              void* d_out, int out_size) {
    const float* node_feats = (const float*)d_in[0];
    const float* edge_attr  = (const float*)d_in[1];
    const float* W_node = (const float*)d_in[2];
    const float* b_node = (const float*)d_in[3];
    const float* W_edge = (const float*)d_in[4];
    const float* b_edge = (const float*)d_in[5];
    const float* W_eij  = (const float*)d_in[6];
    const float* b_eij  = (const float*)d_in[7];
    const float* W_i    = (const float*)d_in[8];
    const float* W_j    = (const float*)d_in[9];
    const float* W_de   = (const float*)d_in[10];
    const float* b_de   = (const float*)d_in[11];
    const float* W_dv1  = (const float*)d_in[12];
    const float* b_dv1  = (const float*)d_in[13];
    const float* W_dv2  = (const float*)d_in[14];
    const float* b_dv2  = (const float*)d_in[15];

    float* h = (float*)d_out;            // (768, 100)
    float* e = h + NATOMS * H;           // (589824, 100)

    // smem: 4*BM*RS + 4*104*RS u32  +  (832 + 1600 + 100) f32
    const int smem_bytes =
        (4 * BM * RS + 4 * 104 * RS) * 4 + (8 * 104 + 1600 + 100) * 4;
    cudaFuncSetAttribute(k_edge, cudaFuncAttributeMaxDynamicSharedMemorySize,
                         smem_bytes);

    int dev = 0, nsm = 148;
    cudaGetDevice(&dev);
    cudaDeviceGetAttribute(&nsm, cudaDevAttrMultiProcessorCount, dev);

    const int NH = NATOMS * H;
    const int WP = (104 * 116 + 255) / 256;

    k_split_w<<<WP, 256>>>(W_eij, 0);
    k_split_w<<<WP, 256>>>(W_de, 1);
    k_init_h<<<(NH + 255) / 256, 256>>>(node_feats, W_node, b_node, h);

    for (int it = 0; it < ITERS; it++) {
        k_fij<<<(2 * NH + 255) / 256, 256>>>(h, W_i, W_j);
        k_dots<<<dim3(48, 48), dim3(16, 16)>>>();
        k_edge<<<nsm, 256, smem_bytes>>>(e, edge_attr, W_edge, b_edge,
                                         b_eij, b_de, it == 0 ? 1 : 0);
        k_reduce_S<<<(NH + 255) / 256, 256>>>();
        k_node1<<<(NH + 255) / 256, 256>>>(W_dv1, b_dv1);
        k_node2<<<(NH + 255) / 256, 256>>>(h, W_dv2, b_dv2);
    }
}

// round 9
// speedup vs baseline: 2.0804x; 1.0161x over previous
#include <cuda_runtime.h>
#include <cuda_bf16.h>

#define NATOMS 768
#define H 100
#define IN_NODE 32
#define IN_EDGE 16
#define ITERS 3
#define NE (NATOMS * NATOMS)       // 589824

#define BM 128                      // e-rows per tile
#define NTILES (NE / BM)            // 4608
#define SEGS 6                      // 768 / 128
#define NT 13                       // n-tiles of 8 (cols 0..103)
#define KC 7                        // k-chunks of 16 (cols 0..111)
#define RS 58                       // row stride in u32 words (116 bf16)
#define ETHREADS 512                // k_edge block size (16 warps)

// ---- scratch (device globals; no allocation allowed) ----
__device__ float g_dots[NE];
__device__ float g_fi[NATOMS * H];
__device__ float g_fj[NATOMS * H];
__device__ float g_PS[SEGS * NATOMS * H];
__device__ float g_S[NATOMS * H];
__device__ float g_dV[NATOMS * H];
// bf16 hi/lo split weights, n-major, padded to 104(n) x 116(k)
__device__ __nv_bfloat16 g_Weij_h[104 * 116];
__device__ __nv_bfloat16 g_Weij_l[104 * 116];
__device__ __nv_bfloat16 g_Wde_h[104 * 116];
__device__ __nv_bfloat16 g_Wde_l[104 * 116];

// ---------------------------------------------------------------------------
__device__ __forceinline__ void mma_bf16(float* d, unsigned a0, unsigned a1,
                                         unsigned a2, unsigned a3,
                                         unsigned b0, unsigned b1) {
    asm volatile(
        "mma.sync.aligned.m16n8k16.row.col.f32.bf16.bf16.f32 "
        "{%0,%1,%2,%3},{%4,%5,%6,%7},{%8,%9},{%0,%1,%2,%3};"
        : "+f"(d[0]), "+f"(d[1]), "+f"(d[2]), "+f"(d[3])
        : "r"(a0), "r"(a1), "r"(a2), "r"(a3), "r"(b0), "r"(b1));
}

// split x,y into bf16 hi/lo pairs packed as u32 (lo = bf16(v - hi))
__device__ __forceinline__ void split_pack(float x, float y, unsigned& hi,
                                           unsigned& lo) {
    __nv_bfloat16 hx = __float2bfloat16(x), hy = __float2bfloat16(y);
    float lx = x - __bfloat162float(hx);
    float ly = y - __bfloat162float(hy);
    __nv_bfloat162 Hp = __halves2bfloat162(hx, hy);
    __nv_bfloat162 Lp = __halves2bfloat162(__float2bfloat16(lx),
                                           __float2bfloat16(ly));
    hi = *reinterpret_cast<unsigned*>(&Hp);
    lo = *reinterpret_cast<unsigned*>(&Lp);
}

// ---------------------------------------------------------------------------
// Split 100x100 fp32 weight into bf16 hi/lo, n-major, padded 104x116.
__global__ void k_split_w(const float* __restrict__ W, int which) {
    int idx = blockIdx.x * blockDim.x + threadIdx.x;
    if (idx >= 104 * 116) return;
    int n = idx / 116, k = idx % 116;
    float v = (k < H && n < H) ? W[k * H + n] : 0.f;
    __nv_bfloat16 h = __float2bfloat16(v);
    __nv_bfloat16 l = __float2bfloat16(v - __bfloat162float(h));
    if (which == 0) { g_Weij_h[idx] = h; g_Weij_l[idx] = l; }
    else           { g_Wde_h[idx]  = h; g_Wde_l[idx]  = l; }
}

// h = node_feats @ W_node + b_node
__global__ void k_init_h(const float* __restrict__ nf, const float* __restrict__ W,
                         const float* __restrict__ b, float* __restrict__ h) {
    int idx = blockIdx.x * blockDim.x + threadIdx.x;
    if (idx >= NATOMS * H) return;
    int n = idx / H, c = idx % H;
    float acc = b[c];
#pragma unroll
    for (int k = 0; k < IN_NODE; k++) acc += nf[n * IN_NODE + k] * W[k * H + c];
    h[idx] = acc;
}

// f_i = h @ W_i ; f_j = h @ W_j
__global__ void k_fij(const float* __restrict__ h, const float* __restrict__ Wi,
                      const float* __restrict__ Wj) {
    int idx = blockIdx.x * blockDim.x + threadIdx.x;
    if (idx >= 2 * NATOMS * H) return;
    int which = (idx < NATOMS * H) ? 0 : 1;
    int t = which ? (idx - NATOMS * H) : idx;
    const float* W = which ? Wj : Wi;
    float* out = which ? g_fj : g_fi;
    int n = t / H, c = t % H;
    float acc = 0.f;
#pragma unroll 4
    for (int k = 0; k < H; k++) acc += __ldg(h + n * H + k) * __ldg(W + k * H + c);
    out[t] = acc;
}

// dots[i][j] = dot(f_i[i], f_j[j]) ; 32x32 tile / block, 2x2 per thread
__global__ void k_dots() {
    __shared__ float sA[32][17];
    __shared__ float sB[32][17];
    int tx = threadIdx.x, ty = threadIdx.y;       // 16x16
    int i0 = blockIdx.y * 32 + ty * 2;
    int j0 = blockIdx.x * 32 + tx * 2;
    float a00 = 0.f, a01 = 0.f, a10 = 0.f, a11 = 0.f;
    int tid = ty * 16 + tx;
    for (int k0 = 0; k0 < H; k0 += 16) {
        // load 32x16 of fi rows and fj rows
        for (int q = tid; q < 32 * 16; q += 256) {
            int r = q >> 4, kk = q & 15;
            int ka = k0 + kk;
            sA[r][kk] = (ka < H) ? g_fi[(blockIdx.y * 32 + r) * H + ka] : 0.f;
            sB[r][kk] = (ka < H) ? g_fj[(blockIdx.x * 32 + r) * H + ka] : 0.f;
        }
        __syncthreads();
#pragma unroll
        for (int kk = 0; kk < 16; kk++) {
            float x0 = sA[ty * 2][kk], x1 = sA[ty * 2 + 1][kk];
            float y0 = sB[tx * 2][kk], y1 = sB[tx * 2 + 1][kk];
            a00 += x0 * y0; a01 += x0 * y1;
            a10 += x1 * y0; a11 += x1 * y1;
        }
        __syncthreads();
    }
    g_dots[i0 * NATOMS + j0] = a00;
    g_dots[i0 * NATOMS + j0 + 1] = a01;
    g_dots[(i0 + 1) * NATOMS + j0] = a10;
    g_dots[(i0 + 1) * NATOMS + j0 + 1] = a11;
}

// ---------------------------------------------------------------------------
// Persistent fused edge kernel, 512 threads (16 warps).
// Row-warps rw=w&7 own rows rw*16..+16; n-halves nh=w>>3 own
// n-tiles [nh*7, nh*7 + (7-nh)).
extern __shared__ unsigned usmem[];

__global__ __launch_bounds__(ETHREADS) void k_edge(
    float* __restrict__ e, const float* __restrict__ ea,
    const float* __restrict__ W_edge, const float* __restrict__ b_edge,
    const float* __restrict__ b_eij, const float* __restrict__ b_de, int first) {
    unsigned* sEh = usmem;
    unsigned* sEl = sEh + BM * RS;
    unsigned* sFh = sEl + BM * RS;
    unsigned* sFl = sFh + BM * RS;
    unsigned* sW  = sFl + BM * RS;                 // 4 * 104*RS
    float* sRed = (float*)(sW + 4 * 104 * RS);     // 8 * 104
    float* sWe  = sRed + 8 * 104;                  // 100 * 16 (c-major)
    float* sbe  = sWe + 1600;                      // 100

    const int tid = threadIdx.x;
    const int w = tid >> 5;
    const int lane = tid & 31;
    const int g = lane >> 2;
    const int tig = lane & 3;
    const int rw = w & 7;
    const int nh = w >> 3;
    const int n0 = nh * 7;
    const int nc = 7 - nh;                         // 7 or 6 n-tiles
    const int rA = rw * 16 + g;

    // ---- stage all weights once; zero F pad words (52..55) once ----
    for (int idx = tid; idx < 104 * RS; idx += ETHREADS) {
        sW[idx]                = ((const unsigned*)g_Weij_h)[idx];
        sW[104 * RS + idx]     = ((const unsigned*)g_Weij_l)[idx];
        sW[2 * 104 * RS + idx] = ((const unsigned*)g_Wde_h)[idx];
        sW[3 * 104 * RS + idx] = ((const unsigned*)g_Wde_l)[idx];
    }
    for (int idx = tid; idx < 1600; idx += ETHREADS) {
        int c = idx / 16, k = idx % 16;
        sWe[idx] = W_edge[k * H + c];
    }
    if (tid < H) sbe[tid] = b_edge[tid];
    for (int idx = tid; idx < BM * 4; idx += ETHREADS) {
        int r = idx >> 2, wd = 52 + (idx & 3);
        sFh[r * RS + wd] = 0u;
        sFl[r * RS + wd] = 0u;
    }
    __syncthreads();

    for (int t = blockIdx.x; t < NTILES; t += gridDim.x) {
        const int i = t / SEGS;
        const int s = t % SEGS;
        const size_t base = (size_t)t * BM * H;

        // ---- stage E tile (split bf16 hi/lo) ----
        if (first) {
            // E = ea_row @ W_edge + b_edge; 4 threads per row
            int r = tid >> 2, p = tid & 3;
            float a[16];
            const float4* ear = (const float4*)(ea + ((size_t)t * BM + r) * IN_EDGE);
            float4 q0 = ear[0], q1 = ear[1], q2 = ear[2], q3 = ear[3];
            a[0]=q0.x;a[1]=q0.y;a[2]=q0.z;a[3]=q0.w; a[4]=q1.x;a[5]=q1.y;a[6]=q1.z;a[7]=q1.w;
            a[8]=q2.x;a[9]=q2.y;a[10]=q2.z;a[11]=q2.w; a[12]=q3.x;a[13]=q3.y;a[14]=q3.z;a[15]=q3.w;
            for (int wd = p; wd < RS; wd += 4) {
                int c0 = wd * 2;
                float v0 = 0.f, v1 = 0.f;
                if (c0 < H) {
                    v0 = sbe[c0]; v1 = sbe[c0 + 1];
#pragma unroll
                    for (int k = 0; k < 16; k++) {
                        v0 += a[k] * sWe[c0 * 16 + k];
                        v1 += a[k] * sWe[(c0 + 1) * 16 + k];
                    }
                }
                unsigned hi, lo;
                split_pack(v0, v1, hi, lo);
                sEh[r * RS + wd] = hi;
                sEl[r * RS + wd] = lo;
            }
        } else {
            for (int idx = tid; idx < BM * RS; idx += ETHREADS) {
                int r = idx / RS, wd = idx - r * RS;
                int c = wd * 2;
                float v0 = 0.f, v1 = 0.f;
                if (c < H) {
                    float2 p = *(const float2*)(e + base + r * H + c);
                    v0 = p.x; v1 = p.y;
                }
                unsigned hi, lo;
                split_pack(v0, v1, hi, lo);
                sEh[idx] = hi;
                sEl[idx] = lo;
            }
        }
        __syncthreads();

        // ---- phase 1: acc = E @ W_eij (3-term bf16) ----
        float acc[7][4];
#pragma unroll
        for (int n = 0; n < 7; n++)
#pragma unroll
            for (int q = 0; q < 4; q++) acc[n][q] = 0.f;

#pragma unroll
        for (int kc = 0; kc < KC; kc++) {
            int ab = rA * RS + kc * 8 + tig;
            unsigned ah0 = sEh[ab],       ah1 = sEh[ab + 8 * RS];
            unsigned ah2 = sEh[ab + 4],   ah3 = sEh[ab + 8 * RS + 4];
            unsigned al0 = sEl[ab],       al1 = sEl[ab + 8 * RS];
            unsigned al2 = sEl[ab + 4],   al3 = sEl[ab + 8 * RS + 4];
#pragma unroll
            for (int nn = 0; nn < 7; nn++) {
                if (nn >= nc) break;
                int bb = ((n0 + nn) * 8 + g) * RS + kc * 8 + tig;
                unsigned bh0 = sW[bb], bh1 = sW[bb + 4];
                unsigned bl0 = sW[104 * RS + bb], bl1 = sW[104 * RS + bb + 4];
                mma_bf16(acc[nn], ah0, ah1, ah2, ah3, bh0, bh1);
                mma_bf16(acc[nn], ah0, ah1, ah2, ah3, bl0, bl1);
                mma_bf16(acc[nn], al0, al1, al2, al3, bh0, bh1);
            }
        }

        // ---- F = relu(acc + b_eij + dots), split -> sF ----
        {
            float d0 = g_dots[i * NATOMS + s * BM + rA];
            float d1 = g_dots[i * NATOMS + s * BM + rA + 8];
#pragma unroll
            for (int nn = 0; nn < 7; nn++) {
                if (nn >= nc) break;
                int n = n0 + nn;
                int c0 = n * 8 + tig * 2;
                float f00 = 0.f, f01 = 0.f, f10 = 0.f, f11 = 0.f;
                if (c0 < H) {
                    float be0 = __ldg(b_eij + c0), be1 = __ldg(b_eij + c0 + 1);
                    f00 = fmaxf(acc[nn][0] + be0 + d0, 0.f);
                    f01 = fmaxf(acc[nn][1] + be1 + d0, 0.f);
                    f10 = fmaxf(acc[nn][2] + be0 + d1, 0.f);
                    f11 = fmaxf(acc[nn][3] + be1 + d1, 0.f);
                }
                unsigned hi, lo;
                int wi = rA * RS + n * 4 + tig;
                split_pack(f00, f01, hi, lo);
                sFh[wi] = hi; sFl[wi] = lo;
                split_pack(f10, f11, hi, lo);
                sFh[wi + 8 * RS] = hi; sFl[wi + 8 * RS] = lo;
            }
        }
        __syncthreads();

        // ---- phase 2: acc = F @ W_de ----
#pragma unroll
        for (int n = 0; n < 7; n++)
#pragma unroll
            for (int q = 0; q < 4; q++) acc[n][q] = 0.f;

#pragma unroll
        for (int kc = 0; kc < KC; kc++) {
            int ab = rA * RS + kc * 8 + tig;
            unsigned ah0 = sFh[ab],       ah1 = sFh[ab + 8 * RS];
            unsigned ah2 = sFh[ab + 4],   ah3 = sFh[ab + 8 * RS + 4];
            unsigned al0 = sFl[ab],       al1 = sFl[ab + 8 * RS];
            unsigned al2 = sFl[ab + 4],   al3 = sFl[ab + 8 * RS + 4];
#pragma unroll
            for (int nn = 0; nn < 7; nn++) {
                if (nn >= nc) break;
                int bb = ((n0 + nn) * 8 + g) * RS + kc * 8 + tig;
                unsigned bh0 = sW[2 * 104 * RS + bb], bh1 = sW[2 * 104 * RS + bb + 4];
                unsigned bl0 = sW[3 * 104 * RS + bb], bl1 = sW[3 * 104 * RS + bb + 4];
                mma_bf16(acc[nn], ah0, ah1, ah2, ah3, bh0, bh1);
                mma_bf16(acc[nn], ah0, ah1, ah2, ah3, bl0, bl1);
                mma_bf16(acc[nn], al0, al1, al2, al3, bh0, bh1);
            }
        }

        // ---- residual writeback + column sums ----
#pragma unroll
        for (int nn = 0; nn < 7; nn++) {
            if (nn >= nc) break;
            int n = n0 + nn;
            int c0 = n * 8 + tig * 2;
            float p0 = 0.f, p1 = 0.f;
            if (c0 < H) {
                float bd0 = __ldg(b_de + c0), bd1 = __ldg(b_de + c0 + 1);
                int wi = rA * RS + n * 4 + tig;
                __nv_bfloat162 Eh0 = *reinterpret_cast<__nv_bfloat162*>(&sEh[wi]);
                __nv_bfloat162 El0 = *reinterpret_cast<__nv_bfloat162*>(&sEl[wi]);
                __nv_bfloat162 Eh1 = *reinterpret_cast<__nv_bfloat162*>(&sEh[wi + 8 * RS]);
                __nv_bfloat162 El1 = *reinterpret_cast<__nv_bfloat162*>(&sEl[wi + 8 * RS]);
                float e00 = __low2float(Eh0) + __low2float(El0);
                float e01 = __high2float(Eh0) + __high2float(El0);
                float e10 = __low2float(Eh1) + __low2float(El1);
                float e11 = __high2float(Eh1) + __high2float(El1);
                float v00 = e00 + acc[nn][0] + bd0;
                float v01 = e01 + acc[nn][1] + bd1;
                float v10 = e10 + acc[nn][2] + bd0;
                float v11 = e11 + acc[nn][3] + bd1;
                *(float2*)(e + base + rA * H + c0) = make_float2(v00, v01);
                *(float2*)(e + base + (rA + 8) * H + c0) = make_float2(v10, v11);
                p0 = v00 + v10;
                p1 = v01 + v11;
            }
            p0 += __shfl_down_sync(0xffffffffu, p0, 16);
            p0 += __shfl_down_sync(0xffffffffu, p0, 8);
            p0 += __shfl_down_sync(0xffffffffu, p0, 4);
            p1 += __shfl_down_sync(0xffffffffu, p1, 16);
            p1 += __shfl_down_sync(0xffffffffu, p1, 8);
            p1 += __shfl_down_sync(0xffffffffu, p1, 4);
            if (lane < 4 && c0 < H) {
                sRed[rw * 104 + c0] = p0;
                sRed[rw * 104 + c0 + 1] = p1;
            }
        }
        __syncthreads();

        if (tid < H) {
            float sum = 0.f;
#pragma unroll
            for (int q = 0; q < 8; q++) sum += sRed[q * 104 + tid];
            g_PS[(s * NATOMS + i) * H + tid] = sum;
        }
        __syncthreads();
    }
}

// ---------------------------------------------------------------------------
__global__ void k_reduce_S() {
    int idx = blockIdx.x * blockDim.x + threadIdx.x;
    if (idx >= NATOMS * H) return;
    float acc = 0.f;
#pragma unroll
    for (int seg = 0; seg < SEGS; seg++) acc += g_PS[seg * NATOMS * H + idx];
    g_S[idx] = acc;
}

__global__ void k_node1(const float* __restrict__ W, const float* __restrict__ b) {
    int idx = blockIdx.x * blockDim.x + threadIdx.x;
    if (idx >= NATOMS * H) return;
    int n = idx / H, c = idx % H;
    float acc = (float)NATOMS * __ldg(b + c);
#pragma unroll 4
    for (int k = 0; k < H; k++) acc += g_S[n * H + k] * __ldg(W + k * H + c);
    g_dV[idx] = acc;
}

__global__ void k_node2(float* __restrict__ h, const float* __restrict__ W,
                        const float* __restrict__ b) {
    int idx = blockIdx.x * blockDim.x + threadIdx.x;
    if (idx >= NATOMS * H) return;
    int n = idx / H, c = idx % H;
    float acc = __ldg(b + c);
#pragma unroll 4
    for (int k = 0; k < H; k++) acc += g_dV[n * H + k] * __ldg(W + k * H + c);
    h[idx] += acc;
}

// ---------------------------------------------------------------------------
extern "C" void kernel_launch(void* const* d_in, const int* in_sizes, int n_in,
                              void* d_out, int out_size) {
    const float* node_feats = (const float*)d_in[0];
    const float* edge_attr  = (const float*)d_in[1];
    const float* W_node = (const float*)d_in[2];
    const float* b_node = (const float*)d_in[3];
    const float* W_edge = (const float*)d_in[4];
    const float* b_edge = (const float*)d_in[5];
    const float* W_eij  = (const float*)d_in[6];
    const float* b_eij  = (const float*)d_in[7];
    const float* W_i    = (const float*)d_in[8];
    const float* W_j    = (const float*)d_in[9];
    const float* W_de   = (const float*)d_in[10];
    const float* b_de   = (const float*)d_in[11];
    const float* W_dv1  = (const float*)d_in[12];
    const float* b_dv1  = (const float*)d_in[13];
    const float* W_dv2  = (const float*)d_in[14];
    const float* b_dv2  = (const float*)d_in[15];

    float* h = (float*)d_out;            // (768, 100)
    float* e = h + NATOMS * H;           // (589824, 100)

    const int smem_bytes =
        (4 * BM * RS + 4 * 104 * RS) * 4 + (8 * 104 + 1600 + 100) * 4;
    cudaFuncSetAttribute(k_edge, cudaFuncAttributeMaxDynamicSharedMemorySize,
                         smem_bytes);

    int dev = 0, nsm = 148;
    cudaGetDevice(&dev);
    cudaDeviceGetAttribute(&nsm, cudaDevAttrMultiProcessorCount, dev);

    const int NH = NATOMS * H;
    const int WP = (104 * 116 + 255) / 256;

    k_split_w<<<WP, 256>>>(W_eij, 0);
    k_split_w<<<WP, 256>>>(W_de, 1);
    k_init_h<<<(NH + 255) / 256, 256>>>(node_feats, W_node, b_node, h);

    for (int it = 0; it < ITERS; it++) {
        k_fij<<<(2 * NH + 255) / 256, 256>>>(h, W_i, W_j);
        k_dots<<<dim3(24, 24), dim3(16, 16)>>>();
        k_edge<<<nsm, ETHREADS, smem_bytes>>>(e, edge_attr, W_edge, b_edge,
                                              b_eij, b_de, it == 0 ? 1 : 0);
        k_reduce_S<<<(NH + 255) / 256, 256>>>();
        k_node1<<<(NH + 255) / 256, 256>>>(W_dv1, b_dv1);
        k_node2<<<(NH + 255) / 256, 256>>>(h, W_dv2, b_dv2);
    }
}

// round 11
// speedup vs baseline: 2.8928x; 1.3905x over previous
#include <cuda_runtime.h>
#include <cuda_bf16.h>

#define NATOMS 768
#define H 100
#define IN_NODE 32
#define IN_EDGE 16
#define ITERS 3
#define NE (NATOMS * NATOMS)       // 589824

#define BM 128
#define NTILES (NE / BM)            // 4608
#define SEGS 6
#define KC 7                        // k16 steps covering 0..111
#define RS 58                       // row stride in u32 words (116 bf16)
#define ETHREADS 512

// smem word offsets for k_edge
#define OFF_WC 0                    // Wc hi/lo: 2 * 6032
#define OFF_WD 12064                // Wde hi/lo: 2 * 6032
#define OFF_FH 24128                // Fsum hi: 7424
#define OFF_FL 31552                // Fsum lo: 7424
#define OFF_RED 38976               // 8*104 f32
#define OFF_WZ 39808                // 1700 f32
#define OFF_WE2 41508               // 1700 f32
#define OFF_BZ 43208                // 100
#define OFF_BDE 43308               // 100
#define OFF_BE 43408                // 100
#define SMEM_WORDS 43508            // 174 KB

// ---- scratch (device globals; no allocation allowed) ----
__device__ float g_dots[NE];
__device__ float g_fi[NATOMS * H];
__device__ float g_fj[NATOMS * H];
__device__ float g_PS[SEGS * NATOMS * H];
__device__ float g_FSrow[NATOMS * H];
__device__ float g_S[NATOMS * H];
__device__ float g_dV[NATOMS * H];
__device__ float g_SEa[NATOMS * IN_EDGE];
__device__ float g_Wc[H * H];              // W_de @ W_eij (fp32)
__device__ float g_Wz[H * 17];             // (W_edge@W_eij)^T padded: [c*17+k]
__device__ float g_We[H * 17];             // W_edge^T padded: [c*17+k]
__device__ float g_bz0[H];                 // b_edge@W_eij + b_eij
__device__ float g_bde[H];                 // b_de@W_eij
// 3-term split weights, n-major 104 x 116 bf16
__device__ __nv_bfloat16 g_Wc_h[104 * 116];
__device__ __nv_bfloat16 g_Wc_l[104 * 116];
__device__ __nv_bfloat16 g_Wde_h[104 * 116];
__device__ __nv_bfloat16 g_Wde_l[104 * 116];

// ---------------------------------------------------------------------------
__device__ __forceinline__ void mma_bf16(float* d, unsigned a0, unsigned a1,
                                         unsigned a2, unsigned a3,
                                         unsigned b0, unsigned b1) {
    asm volatile(
        "mma.sync.aligned.m16n8k16.row.col.f32.bf16.bf16.f32 "
        "{%0,%1,%2,%3},{%4,%5,%6,%7},{%8,%9},{%0,%1,%2,%3};"
        : "+f"(d[0]), "+f"(d[1]), "+f"(d[2]), "+f"(d[3])
        : "r"(a0), "r"(a1), "r"(a2), "r"(a3), "r"(b0), "r"(b1));
}

__device__ __forceinline__ void split_pack(float x, float y, unsigned& hi,
                                           unsigned& lo) {
    __nv_bfloat16 hx = __float2bfloat16(x), hy = __float2bfloat16(y);
    float lx = x - __bfloat162float(hx);
    float ly = y - __bfloat162float(hy);
    __nv_bfloat162 Hp = __halves2bfloat162(hx, hy);
    __nv_bfloat162 Lp = __halves2bfloat162(__float2bfloat16(lx),
                                           __float2bfloat16(ly));
    hi = *reinterpret_cast<unsigned*>(&Hp);
    lo = *reinterpret_cast<unsigned*>(&Lp);
}

// ---------------------------------------------------------------------------
// Wc = W_de @ W_eij (fp32)
__global__ void k_prep_wc(const float* __restrict__ W_de,
                          const float* __restrict__ W_eij) {
    int idx = blockIdx.x * blockDim.x + threadIdx.x;
    if (idx >= H * H) return;
    int k = idx / H, c = idx % H;
    float acc = 0.f;
#pragma unroll 4
    for (int m = 0; m < H; m++) acc += W_de[k * H + m] * W_eij[m * H + c];
    g_Wc[idx] = acc;
}

// Wz, We (transposed padded), bz0, bde
__global__ void k_prep_small(const float* __restrict__ W_edge,
                             const float* __restrict__ W_eij,
                             const float* __restrict__ b_edge,
                             const float* __restrict__ b_eij,
                             const float* __restrict__ b_de) {
    int idx = blockIdx.x * blockDim.x + threadIdx.x;
    if (idx < 1700) {
        int c = idx / 17, k = idx % 17;
        float v = 0.f;
        if (k < 16) {
#pragma unroll 4
            for (int m = 0; m < H; m++) v += W_edge[k * H + m] * W_eij[m * H + c];
        }
        g_Wz[idx] = v;
    } else if (idx < 3400) {
        int j = idx - 1700;
        int c = j / 17, k = j % 17;
        g_We[j] = (k < 16) ? W_edge[k * H + c] : 0.f;
    } else if (idx < 3500) {
        int c = idx - 3400;
        float v = b_eij[c];
#pragma unroll 4
        for (int m = 0; m < H; m++) v += b_edge[m] * W_eij[m * H + c];
        g_bz0[c] = v;
    } else if (idx < 3600) {
        int c = idx - 3500;
        float v = 0.f;
#pragma unroll 4
        for (int m = 0; m < H; m++) v += b_de[m] * W_eij[m * H + c];
        g_bde[c] = v;
    }
}

// split g_Wc -> g_Wc_h/l  (n-major 104x116)
__global__ void k_split_wc() {
    int idx = blockIdx.x * blockDim.x + threadIdx.x;
    if (idx >= 104 * 116) return;
    int n = idx / 116, k = idx % 116;
    float v = (k < H && n < H) ? g_Wc[k * H + n] : 0.f;
    __nv_bfloat16 h = __float2bfloat16(v);
    g_Wc_h[idx] = h;
    g_Wc_l[idx] = __float2bfloat16(v - __bfloat162float(h));
}

__global__ void k_split_wde(const float* __restrict__ W_de) {
    int idx = blockIdx.x * blockDim.x + threadIdx.x;
    if (idx >= 104 * 116) return;
    int n = idx / 116, k = idx % 116;
    float v = (k < H && n < H) ? W_de[k * H + n] : 0.f;
    __nv_bfloat16 h = __float2bfloat16(v);
    g_Wde_h[idx] = h;
    g_Wde_l[idx] = __float2bfloat16(v - __bfloat162float(h));
}

// SEa[i][k] = sum_j ea[(i*768+j)*16+k]
__global__ void k_rowsum_ea(const float* __restrict__ ea) {
    __shared__ float sp[256];
    int i = blockIdx.x;
    int tid = threadIdx.x;
    int k = tid & 15, jg = tid >> 4;
    float part = 0.f;
    for (int j = jg; j < NATOMS; j += 16)
        part += ea[((size_t)i * NATOMS + j) * IN_EDGE + k];
    sp[tid] = part;
    __syncthreads();
    if (tid < 16) {
        float sum = 0.f;
#pragma unroll
        for (int q = 0; q < 16; q++) sum += sp[q * 16 + tid];
        g_SEa[i * IN_EDGE + tid] = sum;
    }
}

// h = node_feats @ W_node + b_node
__global__ void k_init_h(const float* __restrict__ nf, const float* __restrict__ W,
                         const float* __restrict__ b, float* __restrict__ h) {
    int idx = blockIdx.x * blockDim.x + threadIdx.x;
    if (idx >= NATOMS * H) return;
    int n = idx / H, c = idx % H;
    float acc = b[c];
#pragma unroll
    for (int k = 0; k < IN_NODE; k++) acc += nf[n * IN_NODE + k] * W[k * H + c];
    h[idx] = acc;
}

__global__ void k_fij(const float* __restrict__ h, const float* __restrict__ Wi,
                      const float* __restrict__ Wj) {
    int idx = blockIdx.x * blockDim.x + threadIdx.x;
    if (idx >= 2 * NATOMS * H) return;
    int which = (idx < NATOMS * H) ? 0 : 1;
    int t = which ? (idx - NATOMS * H) : idx;
    const float* W = which ? Wj : Wi;
    float* out = which ? g_fj : g_fi;
    int n = t / H, c = t % H;
    float acc = 0.f;
#pragma unroll 4
    for (int k = 0; k < H; k++) acc += __ldg(h + n * H + k) * __ldg(W + k * H + c);
    out[t] = acc;
}

__global__ void k_dots() {
    __shared__ float sA[32][17];
    __shared__ float sB[32][17];
    int tx = threadIdx.x, ty = threadIdx.y;
    int i0 = blockIdx.y * 32 + ty * 2;
    int j0 = blockIdx.x * 32 + tx * 2;
    float a00 = 0.f, a01 = 0.f, a10 = 0.f, a11 = 0.f;
    int tid = ty * 16 + tx;
    for (int k0 = 0; k0 < H; k0 += 16) {
        for (int q = tid; q < 32 * 16; q += 256) {
            int r = q >> 4, kk = q & 15;
            int ka = k0 + kk;
            sA[r][kk] = (ka < H) ? g_fi[(blockIdx.y * 32 + r) * H + ka] : 0.f;
            sB[r][kk] = (ka < H) ? g_fj[(blockIdx.x * 32 + r) * H + ka] : 0.f;
        }
        __syncthreads();
#pragma unroll
        for (int kk = 0; kk < 16; kk++) {
            float x0 = sA[ty * 2][kk], x1 = sA[ty * 2 + 1][kk];
            float y0 = sB[tx * 2][kk], y1 = sB[tx * 2 + 1][kk];
            a00 += x0 * y0; a01 += x0 * y1;
            a10 += x1 * y0; a11 += x1 * y1;
        }
        __syncthreads();
    }
    g_dots[i0 * NATOMS + j0] = a00;
    g_dots[i0 * NATOMS + j0 + 1] = a01;
    g_dots[(i0 + 1) * NATOMS + j0] = a10;
    g_dots[(i0 + 1) * NATOMS + j0 + 1] = a11;
}

// ---------------------------------------------------------------------------
// Persistent fused edge kernel. mode = 1,2,3 (iteration number).
//  mode1: f1 = relu(ea@Wz + bz0 + dots); Fsum := f1           (no MMA!)
//  mode2: f2 = relu(ea@Wz + bz0 + bde + Fsum@Wc + dots); Fsum += f2   (1 GEMM)
//  mode3: f3 = relu(ea@Wz + bz0 + 2*bde + Fsum@Wc + dots);
//         e  = ea@We + b_edge + (Fsum+f3)@W_de + 3*b_de       (2 GEMMs)
// Fsum lives in the e-region of d_out (fp32); mode3 overwrites it with e.
// All modes emit per-tile rowsums of f into g_PS.
extern __shared__ unsigned usmem[];

__global__ __launch_bounds__(ETHREADS) void k_edge(
    float* __restrict__ efs, const float* __restrict__ ea,
    const float* __restrict__ b_de_, const float* __restrict__ b_edge_,
    int mode) {
    unsigned* sWc = usmem + OFF_WC;
    unsigned* sWd = usmem + OFF_WD;
    unsigned* sFh = usmem + OFF_FH;
    unsigned* sFl = usmem + OFF_FL;
    float* sRed = (float*)(usmem + OFF_RED);
    float* sWz = (float*)(usmem + OFF_WZ);
    float* sWe = (float*)(usmem + OFF_WE2);
    float* sbz = (float*)(usmem + OFF_BZ);
    float* sbd = (float*)(usmem + OFF_BDE);
    float* sbe = (float*)(usmem + OFF_BE);

    const int tid = threadIdx.x;
    const int w = tid >> 5;
    const int lane = tid & 31;
    const int g = lane >> 2;
    const int tig = lane & 3;
    const int rw = w & 7;
    const int nh = w >> 3;
    const int n0 = nh * 7;
    const int nc = 7 - nh;
    const int rA = rw * 16 + g;
    const float bf = (float)(mode - 1);

    // ---- stage weights once ----
    for (int idx = tid; idx < 104 * RS; idx += ETHREADS) {
        sWc[idx]        = ((const unsigned*)g_Wc_h)[idx];
        sWc[6032 + idx] = ((const unsigned*)g_Wc_l)[idx];
        sWd[idx]        = ((const unsigned*)g_Wde_h)[idx];
        sWd[6032 + idx] = ((const unsigned*)g_Wde_l)[idx];
    }
    for (int idx = tid; idx < 1700; idx += ETHREADS) {
        sWz[idx] = g_Wz[idx];
        sWe[idx] = g_We[idx];
    }
    if (tid < H) {
        sbz[tid] = g_bz0[tid];
        sbd[tid] = g_bde[tid];
        sbe[tid] = b_edge_[tid];
    }
    __syncthreads();

    for (int t = blockIdx.x; t < NTILES; t += gridDim.x) {
        const int i = t / SEGS;
        const int s = t % SEGS;
        const size_t base = (size_t)t * BM * H;

        // ---- stage Fsum tile (modes 2,3) ----
        if (mode >= 2) {
            for (int idx = tid; idx < BM * RS; idx += ETHREADS) {
                int r = idx / RS, wd = idx - r * RS;
                float v0 = 0.f, v1 = 0.f;
                if (wd * 2 < H) {
                    float2 p2 = *(const float2*)(efs + base + r * H + wd * 2);
                    v0 = p2.x; v1 = p2.y;
                }
                unsigned hi, lo;
                split_pack(v0, v1, hi, lo);
                sFh[idx] = hi;
                sFl[idx] = lo;
            }
        }
        __syncthreads();

        // ---- MMA: acc = Fsum @ Wc (3-term) ----
        float acc[7][4];
#pragma unroll
        for (int n = 0; n < 7; n++)
#pragma unroll
            for (int q = 0; q < 4; q++) acc[n][q] = 0.f;

        if (mode >= 2) {
#pragma unroll
            for (int kc = 0; kc < KC; kc++) {
                int ab = rA * RS + kc * 8 + tig;
                unsigned ah0 = sFh[ab],     ah1 = sFh[ab + 8 * RS];
                unsigned ah2 = sFh[ab + 4], ah3 = sFh[ab + 8 * RS + 4];
                unsigned al0 = sFl[ab],     al1 = sFl[ab + 8 * RS];
                unsigned al2 = sFl[ab + 4], al3 = sFl[ab + 8 * RS + 4];
#pragma unroll
                for (int nn = 0; nn < 7; nn++) {
                    if (nn >= nc) break;
                    int bb = ((n0 + nn) * 8 + g) * RS + kc * 8 + tig;
                    unsigned bh0 = sWc[bb], bh1 = sWc[bb + 4];
                    unsigned bl0 = sWc[6032 + bb], bl1 = sWc[6032 + bb + 4];
                    mma_bf16(acc[nn], ah0, ah1, ah2, ah3, bh0, bh1);
                    mma_bf16(acc[nn], ah0, ah1, ah2, ah3, bl0, bl1);
                    mma_bf16(acc[nn], al0, al1, al2, al3, bh0, bh1);
                }
            }
        }

        // ---- load ea rows for z-compute ----
        float a0[16], a1[16];
        {
            const float4* p0 = (const float4*)(ea + ((size_t)t * BM + rA) * IN_EDGE);
            const float4* p1 = (const float4*)(ea + ((size_t)t * BM + rA + 8) * IN_EDGE);
#pragma unroll
            for (int q = 0; q < 4; q++) {
                float4 v = p0[q];
                a0[q * 4] = v.x; a0[q * 4 + 1] = v.y; a0[q * 4 + 2] = v.z; a0[q * 4 + 3] = v.w;
                v = p1[q];
                a1[q * 4] = v.x; a1[q * 4 + 1] = v.y; a1[q * 4 + 2] = v.z; a1[q * 4 + 3] = v.w;
            }
        }
        const float d0 = g_dots[i * NATOMS + s * BM + rA];
        const float d1 = g_dots[i * NATOMS + s * BM + rA + 8];

        // ---- f = relu(acc + z + bias + dots); rowsums; Fsum/e handling ----
        float fs[7][4];   // mode3: Fsum + f
#pragma unroll
        for (int nn = 0; nn < 7; nn++) {
            if (nn >= nc) break;
            const int n = n0 + nn;
            const int c0 = n * 8 + tig * 2;
            float f00 = 0.f, f01 = 0.f, f10 = 0.f, f11 = 0.f;
            if (c0 < H) {
                float z00 = 0.f, z01 = 0.f, z10 = 0.f, z11 = 0.f;
#pragma unroll
                for (int k = 0; k < 16; k++) {
                    float w0 = sWz[c0 * 17 + k];
                    float w1 = sWz[(c0 + 1) * 17 + k];
                    z00 += a0[k] * w0; z01 += a0[k] * w1;
                    z10 += a1[k] * w0; z11 += a1[k] * w1;
                }
                float bias0 = sbz[c0] + bf * sbd[c0];
                float bias1 = sbz[c0 + 1] + bf * sbd[c0 + 1];
                f00 = fmaxf(acc[nn][0] + z00 + bias0 + d0, 0.f);
                f01 = fmaxf(acc[nn][1] + z01 + bias1 + d0, 0.f);
                f10 = fmaxf(acc[nn][2] + z10 + bias0 + d1, 0.f);
                f11 = fmaxf(acc[nn][3] + z11 + bias1 + d1, 0.f);
            }
            // rowsum partials of f
            float p0 = f00 + f10, p1 = f01 + f11;
            p0 += __shfl_down_sync(0xffffffffu, p0, 16);
            p0 += __shfl_down_sync(0xffffffffu, p0, 8);
            p0 += __shfl_down_sync(0xffffffffu, p0, 4);
            p1 += __shfl_down_sync(0xffffffffu, p1, 16);
            p1 += __shfl_down_sync(0xffffffffu, p1, 8);
            p1 += __shfl_down_sync(0xffffffffu, p1, 4);
            if (lane < 4 && c0 < H) {
                sRed[rw * 104 + c0] = p0;
                sRed[rw * 104 + c0 + 1] = p1;
            }
            if (c0 < H) {
                const int wi = rA * RS + n * 4 + tig;
                float o00 = 0.f, o01 = 0.f, o10 = 0.f, o11 = 0.f;
                if (mode >= 2) {
                    __nv_bfloat162 H0 = *reinterpret_cast<__nv_bfloat162*>(&sFh[wi]);
                    __nv_bfloat162 L0 = *reinterpret_cast<__nv_bfloat162*>(&sFl[wi]);
                    __nv_bfloat162 H1 = *reinterpret_cast<__nv_bfloat162*>(&sFh[wi + 8 * RS]);
                    __nv_bfloat162 L1 = *reinterpret_cast<__nv_bfloat162*>(&sFl[wi + 8 * RS]);
                    o00 = __low2float(H0) + __low2float(L0);
                    o01 = __high2float(H0) + __high2float(L0);
                    o10 = __low2float(H1) + __low2float(L1);
                    o11 = __high2float(H1) + __high2float(L1);
                }
                if (mode <= 2) {
                    // write updated Fsum
                    *(float2*)(efs + base + rA * H + c0) = make_float2(o00 + f00, o01 + f01);
                    *(float2*)(efs + base + (rA + 8) * H + c0) = make_float2(o10 + f10, o11 + f11);
                } else {
                    fs[nn][0] = o00 + f00; fs[nn][1] = o01 + f01;
                    fs[nn][2] = o10 + f10; fs[nn][3] = o11 + f11;
                }
            }
        }

        if (mode <= 2) {
            __syncthreads();
            if (tid < H) {
                float sum = 0.f;
#pragma unroll
                for (int q = 0; q < 8; q++) sum += sRed[q * 104 + tid];
                g_PS[(s * NATOMS + i) * H + tid] = sum;
            }
            __syncthreads();
            continue;
        }

        // ---- mode3: Fsum3 -> sF in place, then MMA2 = Fsum3 @ W_de ----
        __syncthreads();   // all MMA1 A-reads + sRed writes complete
        if (tid < H) {
            float sum = 0.f;
#pragma unroll
            for (int q = 0; q < 8; q++) sum += sRed[q * 104 + tid];
            g_PS[(s * NATOMS + i) * H + tid] = sum;
        }
#pragma unroll
        for (int nn = 0; nn < 7; nn++) {
            if (nn >= nc) break;
            const int n = n0 + nn;
            const int c0 = n * 8 + tig * 2;
            if (c0 < H) {
                const int wi = rA * RS + n * 4 + tig;
                unsigned hi, lo;
                split_pack(fs[nn][0], fs[nn][1], hi, lo);
                sFh[wi] = hi; sFl[wi] = lo;
                split_pack(fs[nn][2], fs[nn][3], hi, lo);
                sFh[wi + 8 * RS] = hi; sFl[wi + 8 * RS] = lo;
            }
        }
        __syncthreads();

#pragma unroll
        for (int n = 0; n < 7; n++)
#pragma unroll
            for (int q = 0; q < 4; q++) acc[n][q] = 0.f;
#pragma unroll
        for (int kc = 0; kc < KC; kc++) {
            int ab = rA * RS + kc * 8 + tig;
            unsigned ah0 = sFh[ab],     ah1 = sFh[ab + 8 * RS];
            unsigned ah2 = sFh[ab + 4], ah3 = sFh[ab + 8 * RS + 4];
            unsigned al0 = sFl[ab],     al1 = sFl[ab + 8 * RS];
            unsigned al2 = sFl[ab + 4], al3 = sFl[ab + 8 * RS + 4];
#pragma unroll
            for (int nn = 0; nn < 7; nn++) {
                if (nn >= nc) break;
                int bb = ((n0 + nn) * 8 + g) * RS + kc * 8 + tig;
                unsigned bh0 = sWd[bb], bh1 = sWd[bb + 4];
                unsigned bl0 = sWd[6032 + bb], bl1 = sWd[6032 + bb + 4];
                mma_bf16(acc[nn], ah0, ah1, ah2, ah3, bh0, bh1);
                mma_bf16(acc[nn], ah0, ah1, ah2, ah3, bl0, bl1);
                mma_bf16(acc[nn], al0, al1, al2, al3, bh0, bh1);
            }
        }

        // ---- e = ea@We + b_edge + acc + 3*b_de ----
#pragma unroll
        for (int nn = 0; nn < 7; nn++) {
            if (nn >= nc) break;
            const int n = n0 + nn;
            const int c0 = n * 8 + tig * 2;
            if (c0 < H) {
                float z00 = 0.f, z01 = 0.f, z10 = 0.f, z11 = 0.f;
#pragma unroll
                for (int k = 0; k < 16; k++) {
                    float w0 = sWe[c0 * 17 + k];
                    float w1 = sWe[(c0 + 1) * 17 + k];
                    z00 += a0[k] * w0; z01 += a0[k] * w1;
                    z10 += a1[k] * w0; z11 += a1[k] * w1;
                }
                float bias0 = sbe[c0] + 3.f * __ldg(b_de_ + c0);
                float bias1 = sbe[c0 + 1] + 3.f * __ldg(b_de_ + c0 + 1);
                *(float2*)(efs + base + rA * H + c0) =
                    make_float2(z00 + bias0 + acc[nn][0], z01 + bias1 + acc[nn][1]);
                *(float2*)(efs + base + (rA + 8) * H + c0) =
                    make_float2(z10 + bias0 + acc[nn][2], z11 + bias1 + acc[nn][3]);
            }
        }
        __syncthreads();
    }
}

// ---------------------------------------------------------------------------
__global__ void k_accum_FSrow(int first) {
    int idx = blockIdx.x * blockDim.x + threadIdx.x;
    if (idx >= NATOMS * H) return;
    float acc = 0.f;
#pragma unroll
    for (int seg = 0; seg < SEGS; seg++) acc += g_PS[seg * NATOMS * H + idx];
    g_FSrow[idx] = first ? acc : (g_FSrow[idx] + acc);
}

// S_t = SEa@W_edge + N*b_edge + FSrow@W_de + N*t*b_de
__global__ void k_S(const float* __restrict__ W_edge, const float* __restrict__ b_edge,
                    const float* __restrict__ W_de, const float* __restrict__ b_de,
                    int t) {
    int idx = blockIdx.x * blockDim.x + threadIdx.x;
    if (idx >= NATOMS * H) return;
    int i = idx / H, c = idx % H;
    float acc = (float)NATOMS * (__ldg(b_edge + c) + (float)t * __ldg(b_de + c));
#pragma unroll
    for (int k = 0; k < IN_EDGE; k++)
        acc += g_SEa[i * IN_EDGE + k] * __ldg(W_edge + k * H + c);
#pragma unroll 4
    for (int k = 0; k < H; k++)
        acc += g_FSrow[i * H + k] * __ldg(W_de + k * H + c);
    g_S[idx] = acc;
}

__global__ void k_node1(const float* __restrict__ W, const float* __restrict__ b) {
    int idx = blockIdx.x * blockDim.x + threadIdx.x;
    if (idx >= NATOMS * H) return;
    int n = idx / H, c = idx % H;
    float acc = (float)NATOMS * __ldg(b + c);
#pragma unroll 4
    for (int k = 0; k < H; k++) acc += g_S[n * H + k] * __ldg(W + k * H + c);
    g_dV[idx] = acc;
}

__global__ void k_node2(float* __restrict__ h, const float* __restrict__ W,
                        const float* __restrict__ b) {
    int idx = blockIdx.x * blockDim.x + threadIdx.x;
    if (idx >= NATOMS * H) return;
    int n = idx / H, c = idx % H;
    float acc = __ldg(b + c);
#pragma unroll 4
    for (int k = 0; k < H; k++) acc += g_dV[n * H + k] * __ldg(W + k * H + c);
    h[idx] += acc;
}

// ---------------------------------------------------------------------------
extern "C" void kernel_launch(void* const* d_in, const int* in_sizes, int n_in,
                              void* d_out, int out_size) {
    const float* node_feats = (const float*)d_in[0];
    const float* edge_attr  = (const float*)d_in[1];
    const float* W_node = (const float*)d_in[2];
    const float* b_node = (const float*)d_in[3];
    const float* W_edge = (const float*)d_in[4];
    const float* b_edge = (const float*)d_in[5];
    const float* W_eij  = (const float*)d_in[6];
    const float* b_eij  = (const float*)d_in[7];
    const float* W_i    = (const float*)d_in[8];
    const float* W_j    = (const float*)d_in[9];
    const float* W_de   = (const float*)d_in[10];
    const float* b_de   = (const float*)d_in[11];
    const float* W_dv1  = (const float*)d_in[12];
    const float* b_dv1  = (const float*)d_in[13];
    const float* W_dv2  = (const float*)d_in[14];
    const float* b_dv2  = (const float*)d_in[15];

    float* h = (float*)d_out;            // (768, 100)
    float* e = h + NATOMS * H;           // Fsum during iters 1-2, final e after iter 3

    const int smem_bytes = SMEM_WORDS * 4;
    cudaFuncSetAttribute(k_edge, cudaFuncAttributeMaxDynamicSharedMemorySize,
                         smem_bytes);

    int dev = 0, nsm = 148;
    cudaGetDevice(&dev);
    cudaDeviceGetAttribute(&nsm, cudaDevAttrMultiProcessorCount, dev);

    const int NH = NATOMS * H;

    // one-time prep
    k_prep_wc<<<(H * H + 255) / 256, 256>>>(W_de, W_eij);
    k_prep_small<<<(3600 + 255) / 256, 256>>>(W_edge, W_eij, b_edge, b_eij, b_de);
    k_split_wc<<<(104 * 116 + 255) / 256, 256>>>();
    k_split_wde<<<(104 * 116 + 255) / 256, 256>>>(W_de);
    k_rowsum_ea<<<NATOMS, 256>>>(edge_attr);
    k_init_h<<<(NH + 255) / 256, 256>>>(node_feats, W_node, b_node, h);

    for (int it = 0; it < ITERS; it++) {
        k_fij<<<(2 * NH + 255) / 256, 256>>>(h, W_i, W_j);
        k_dots<<<dim3(24, 24), dim3(16, 16)>>>();
        k_edge<<<nsm, ETHREADS, smem_bytes>>>(e, edge_attr, b_de, b_edge, it + 1);
        k_accum_FSrow<<<(NH + 255) / 256, 256>>>(it == 0 ? 1 : 0);
        k_S<<<(NH + 255) / 256, 256>>>(W_edge, b_edge, W_de, b_de, it + 1);
        k_node1<<<(NH + 255) / 256, 256>>>(W_dv1, b_dv1);
        k_node2<<<(NH + 255) / 256, 256>>>(h, W_dv2, b_dv2);
    }
}